// round 1
// baseline (speedup 1.0000x reference)
#include <cuda_runtime.h>
#include <math.h>

#define BATCH 1024
#define NV    6890
#define NJ    24

// ---------------- scratch (device globals; no allocation) ----------------
__device__ float g_JS[NJ * 30];      // J_regressor @ shapedirs  [j][k][n]
__device__ float g_JT[NJ * 3];       // J_regressor @ v_template [j][k]
__device__ float g_PF[BATCH * 96];   // pose_feat padded to 96 (93..95 = 0)
__device__ float g_GS[BATCH * 288];  // skinning matrices [b][j][3][4], trans folded in

__constant__ int c_par[24] = {-1,0,0,0,1,2,3,4,5,6,7,8,9,9,9,12,13,14,16,17,18,19,20,21};

// ---------------- kernel 0: JS / JT reduction over V ----------------
__global__ void k0_js(const float* __restrict__ Jreg,
                      const float* __restrict__ sdirs,
                      const float* __restrict__ vtemp)
{
    int j = blockIdx.x;
    int t = threadIdx.x;
    float acc[33];
#pragma unroll
    for (int p = 0; p < 33; ++p) acc[p] = 0.f;
    for (int v = t; v < NV; v += 256) {
        float jr = Jreg[j * NV + v];
        const float* sp = sdirs + v * 30;
#pragma unroll
        for (int p = 0; p < 30; ++p) acc[p] = fmaf(jr, sp[p], acc[p]);
        const float* vp = vtemp + v * 3;
#pragma unroll
        for (int k = 0; k < 3; ++k) acc[30 + k] = fmaf(jr, vp[k], acc[30 + k]);
    }
    __shared__ float red[256][33];
#pragma unroll
    for (int p = 0; p < 33; ++p) red[t][p] = acc[p];
    __syncthreads();
    if (t < 33) {
        float s = 0.f;
        for (int i = 0; i < 256; ++i) s += red[i][t];
        if (t < 30) g_JS[j * 30 + t] = s;
        else        g_JT[j * 3 + (t - 30)] = s;
    }
}

// ---------------- kernel 1: per-batch pose feat, R, J, chain, G_skin ----------------
__global__ void k1_batch(const float* __restrict__ pose,
                         const float* __restrict__ betas,
                         const float* __restrict__ trans,
                         float* __restrict__ outJt)
{
    int b = blockIdx.x;
    int lane = threadIdx.x;
    __shared__ float Rm[24][9];
    __shared__ float Jm[24][3];
    __shared__ float Gm[24][12];
    __shared__ float bet[10];
    if (lane < 10) bet[lane] = betas[b * 10 + lane];
    __syncwarp();
    if (lane < 24) {
        float tx = pose[b * 72 + lane * 3 + 0];
        float ty = pose[b * 72 + lane * 3 + 1];
        float tz = pose[b * 72 + lane * 3 + 2];
        float ax = tx + 1e-8f, ay = ty + 1e-8f, az = tz + 1e-8f;
        float angle = sqrtf(ax * ax + ay * ay + az * az);
        float inv = 1.f / angle;
        float nx = tx * inv, ny = ty * inv, nz = tz * inv;
        float half = 0.5f * angle;
        float s = sinf(half), c = cosf(half);
        if (lane > 0) {
            float* pfo = g_PF + b * 96 + lane * 4 - 4;
            pfo[0] = s * nx; pfo[1] = s * ny; pfo[2] = s * nz; pfo[3] = c - 1.f;
        }
        float qw = c, qx = s * nx, qy = s * ny, qz = s * nz;
        float qn = rsqrtf(qw * qw + qx * qx + qy * qy + qz * qz);
        qw *= qn; qx *= qn; qy *= qn; qz *= qn;
        float w2 = qw * qw, x2 = qx * qx, y2 = qy * qy, z2 = qz * qz;
        float wx = qw * qx, wy = qw * qy, wz = qw * qz;
        float xy = qx * qy, xz = qx * qz, yz = qy * qz;
        Rm[lane][0] = w2 + x2 - y2 - z2; Rm[lane][1] = 2.f*xy - 2.f*wz; Rm[lane][2] = 2.f*wy + 2.f*xz;
        Rm[lane][3] = 2.f*wz + 2.f*xy;  Rm[lane][4] = w2 - x2 + y2 - z2; Rm[lane][5] = 2.f*yz - 2.f*wx;
        Rm[lane][6] = 2.f*xz - 2.f*wy;  Rm[lane][7] = 2.f*wx + 2.f*yz;  Rm[lane][8] = w2 - x2 - y2 + z2;
#pragma unroll
        for (int k = 0; k < 3; ++k) {
            float jv = g_JT[lane * 3 + k];
#pragma unroll
            for (int n = 0; n < 10; ++n) jv = fmaf(g_JS[lane * 30 + k * 10 + n], bet[n], jv);
            Jm[lane][k] = jv;
        }
    } else if (lane == 24) {
        g_PF[b * 96 + 92] = bet[1];
        g_PF[b * 96 + 93] = 0.f; g_PF[b * 96 + 94] = 0.f; g_PF[b * 96 + 95] = 0.f;
    }
    __syncwarp();
    if (lane < 12) {
        int r = lane >> 2, cc = lane & 3;
        Gm[0][lane] = (cc < 3) ? Rm[0][r * 3 + cc] : Jm[0][r];
    }
    __syncwarp();
    for (int i = 1; i < NJ; ++i) {
        int p = c_par[i];
        if (lane < 12) {
            int r = lane >> 2, cc = lane & 3;
            float l0, l1, l2, add = 0.f;
            if (cc < 3) { l0 = Rm[i][cc]; l1 = Rm[i][3 + cc]; l2 = Rm[i][6 + cc]; }
            else {
                l0 = Jm[i][0] - Jm[p][0]; l1 = Jm[i][1] - Jm[p][1]; l2 = Jm[i][2] - Jm[p][2];
                add = Gm[p][r * 4 + 3];
            }
            Gm[i][lane] = fmaf(Gm[p][r*4+0], l0, fmaf(Gm[p][r*4+1], l1, fmaf(Gm[p][r*4+2], l2, add)));
        }
        __syncwarp();
    }
    float t0 = trans[b * 3 + 0], t1 = trans[b * 3 + 1], t2 = trans[b * 3 + 2];
    if (lane < 24) {
        outJt[(b * 24 + lane) * 3 + 0] = Gm[lane][3]  + t0;
        outJt[(b * 24 + lane) * 3 + 1] = Gm[lane][7]  + t1;
        outJt[(b * 24 + lane) * 3 + 2] = Gm[lane][11] + t2;
    }
    __syncwarp();
    for (int idx = lane; idx < 288; idx += 32) {
        int j = idx / 12, e = idx % 12;
        int r = e >> 2, cc = e & 3;
        float val = Gm[j][e];
        if (cc == 3) {
            val = Gm[j][r*4+3] - (Gm[j][r*4+0]*Jm[j][0] + Gm[j][r*4+1]*Jm[j][1] + Gm[j][r*4+2]*Jm[j][2]);
            val += (r == 0 ? t0 : (r == 1 ? t1 : t2));
        }
        g_GS[b * 288 + idx] = val;
    }
}

// ---------------- kernel 2: the heavy fused kernel ----------------
// smem layout (floats)
#define SM_PD 0                       // 8944  posedirs tile [96 rows][93]
#define SM_PF 8944                    // 3072  pose_feat [32][96]
#define SM_GS 12016                   // 9344  G_skin [32][292 pad]
#define SM_SD 21360                   // 1056  shapedirs [32][33 pad]
#define SM_WT 22416                   // 800   weights [32][25 pad]
#define SM_VT 23216                   // 96    v_template [32][3]
#define SM_BT 23312                   // 320   betas [32][10]
#define SM_VP 23632                   // 3168  staging [32][33*3]
#define SM_TOTAL 26800
#define SMEM_BYTES (SM_TOTAL * 4)

__global__ void __launch_bounds__(128) k2_main(
    const float* __restrict__ betas,
    const float* __restrict__ v_template,
    const float* __restrict__ shapedirs,
    const float* __restrict__ posedirs,
    const float* __restrict__ weights,
    float* __restrict__ out)
{
    extern __shared__ float sm[];
    const int tid = threadIdx.x;
    const int vt0 = blockIdx.x * 32;
    const int bt0 = blockIdx.y * 32;
    const int nv = (NV - vt0) < 32 ? (NV - vt0) : 32;

    // ---- cooperative loads (all coalesced in GMEM) ----
    {
        int base = vt0 * 3 * 93;
        int cnt = nv * 3 * 93;
        for (int i = tid; i < cnt; i += 128) sm[SM_PD + i] = posedirs[base + i];
        // zero the tiny tail that the f>92 overread can touch (pf there is 0, avoid NaN*0)
        for (int i = cnt + tid; i < cnt + 16 && i < 8944; i += 128) sm[SM_PD + i] = 0.f;
        for (int i = tid; i < 32 * 96; i += 128) sm[SM_PF + i] = g_PF[bt0 * 96 + i];
        for (int i = tid; i < 32 * 288; i += 128) {
            int bb = i / 288, e = i % 288;
            sm[SM_GS + bb * 292 + e] = g_GS[bt0 * 288 + i];
        }
        for (int i = tid; i < nv * 30; i += 128) {
            int v = i / 30, n = i % 30;
            sm[SM_SD + v * 33 + n] = shapedirs[vt0 * 30 + i];
        }
        for (int i = tid; i < nv * 24; i += 128) {
            int v = i / 24, j = i % 24;
            sm[SM_WT + v * 25 + j] = weights[vt0 * 24 + i];
        }
        for (int i = tid; i < nv * 3; i += 128) sm[SM_VT + i] = v_template[vt0 * 3 + i];
        for (int i = tid; i < 32 * 10; i += 128) sm[SM_BT + i] = betas[bt0 * 10 + i];
    }
    __syncthreads();

    const int vlane = tid & 31;
    const int wq = tid >> 5;                      // warp -> batch subset {wq, wq+4, ...}
    const bool valid = (vt0 + vlane) < NV;
    const size_t R1 = (size_t)BATCH * NV * 3;     // v_posed region
    const size_t R2 = 2 * R1;                     // v_shaped region

    float acc[3][8];
    // ---- phase 1a: v_shaped ----
    {
        float sdr[30];
#pragma unroll
        for (int n = 0; n < 30; ++n) sdr[n] = sm[SM_SD + vlane * 33 + n];
        float vtr0 = sm[SM_VT + vlane * 3 + 0];
        float vtr1 = sm[SM_VT + vlane * 3 + 1];
        float vtr2 = sm[SM_VT + vlane * 3 + 2];
#pragma unroll
        for (int bb = 0; bb < 8; ++bb) {
            int bl = wq + bb * 4;
            float s0 = vtr0, s1 = vtr1, s2 = vtr2;
#pragma unroll
            for (int n = 0; n < 10; ++n) {
                float be = sm[SM_BT + bl * 10 + n];
                s0 = fmaf(sdr[n], be, s0);
                s1 = fmaf(sdr[10 + n], be, s1);
                s2 = fmaf(sdr[20 + n], be, s2);
            }
            acc[0][bb] = s0; acc[1][bb] = s1; acc[2][bb] = s2;
            if (valid) {
                size_t o = ((size_t)(bt0 + bl) * NV + vt0 + vlane) * 3;
                out[R2 + o + 0] = s0; out[R2 + o + 1] = s1; out[R2 + o + 2] = s2;
            }
        }
    }
    // ---- phase 1b: posedirs blend (K=93, padded to 96; pf[93..95]=0) ----
    {
        const float* pdp = sm + SM_PD + vlane * 279;
        for (int f = 0; f < 96; f += 4) {
            float4 pfv[8];
#pragma unroll
            for (int bb = 0; bb < 8; ++bb)
                pfv[bb] = *reinterpret_cast<const float4*>(sm + SM_PF + (wq + bb * 4) * 96 + f);
#pragma unroll
            for (int k = 0; k < 3; ++k) {
                float p0 = pdp[k * 93 + f + 0];
                float p1 = pdp[k * 93 + f + 1];
                float p2 = pdp[k * 93 + f + 2];
                float p3 = pdp[k * 93 + f + 3];
#pragma unroll
                for (int bb = 0; bb < 8; ++bb) {
                    float a = acc[k][bb];
                    a = fmaf(p0, pfv[bb].x, a);
                    a = fmaf(p1, pfv[bb].y, a);
                    a = fmaf(p2, pfv[bb].z, a);
                    a = fmaf(p3, pfv[bb].w, a);
                    acc[k][bb] = a;
                }
            }
        }
    }
    // ---- store v_posed + stage for skinning ----
#pragma unroll
    for (int bb = 0; bb < 8; ++bb) {
        int bl = wq + bb * 4;
        if (valid) {
            size_t o = ((size_t)(bt0 + bl) * NV + vt0 + vlane) * 3;
            out[R1 + o + 0] = acc[0][bb];
            out[R1 + o + 1] = acc[1][bb];
            out[R1 + o + 2] = acc[2][bb];
        }
        sm[SM_VP + vlane * 99 + bl * 3 + 0] = acc[0][bb];
        sm[SM_VP + vlane * 99 + bl * 3 + 1] = acc[1][bb];
        sm[SM_VP + vlane * 99 + bl * 3 + 2] = acc[2][bb];
    }
    __syncthreads();
    // ---- phase 2: skinning, remapped to 4 vertices x 2 batches per thread ----
    {
        const int vset = (tid & 7) * 4;
        const int bp = (tid >> 3) * 2;
        float vh[4][2][3];
#pragma unroll
        for (int vi = 0; vi < 4; ++vi)
#pragma unroll
            for (int b2 = 0; b2 < 2; ++b2)
#pragma unroll
                for (int k = 0; k < 3; ++k)
                    vh[vi][b2][k] = sm[SM_VP + (vset + vi) * 99 + (bp + b2) * 3 + k];
        float av[4][2][3];
#pragma unroll
        for (int vi = 0; vi < 4; ++vi)
#pragma unroll
            for (int b2 = 0; b2 < 2; ++b2)
#pragma unroll
                for (int k = 0; k < 3; ++k) av[vi][b2][k] = 0.f;
#pragma unroll 4
        for (int j = 0; j < 24; ++j) {
            float wv[4];
#pragma unroll
            for (int vi = 0; vi < 4; ++vi) wv[vi] = sm[SM_WT + (vset + vi) * 25 + j];
#pragma unroll
            for (int b2 = 0; b2 < 2; ++b2) {
                const float* gp = sm + SM_GS + (bp + b2) * 292 + j * 12;
                float4 g0 = *reinterpret_cast<const float4*>(gp);
                float4 g1 = *reinterpret_cast<const float4*>(gp + 4);
                float4 g2 = *reinterpret_cast<const float4*>(gp + 8);
#pragma unroll
                for (int vi = 0; vi < 4; ++vi) {
                    float x = vh[vi][b2][0], y = vh[vi][b2][1], z = vh[vi][b2][2];
                    float tx = fmaf(g0.x, x, fmaf(g0.y, y, fmaf(g0.z, z, g0.w)));
                    float ty = fmaf(g1.x, x, fmaf(g1.y, y, fmaf(g1.z, z, g1.w)));
                    float tz = fmaf(g2.x, x, fmaf(g2.y, y, fmaf(g2.z, z, g2.w)));
                    av[vi][b2][0] = fmaf(wv[vi], tx, av[vi][b2][0]);
                    av[vi][b2][1] = fmaf(wv[vi], ty, av[vi][b2][1]);
                    av[vi][b2][2] = fmaf(wv[vi], tz, av[vi][b2][2]);
                }
            }
        }
#pragma unroll
        for (int vi = 0; vi < 4; ++vi)
#pragma unroll
            for (int b2 = 0; b2 < 2; ++b2)
#pragma unroll
                for (int k = 0; k < 3; ++k)
                    sm[SM_VP + (vset + vi) * 99 + (bp + b2) * 3 + k] = av[vi][b2][k];
    }
    __syncthreads();
    // ---- phase 3: coalesced store of v ----
#pragma unroll
    for (int bb = 0; bb < 8; ++bb) {
        int bl = wq + bb * 4;
        if (valid) {
            size_t o = ((size_t)(bt0 + bl) * NV + vt0 + vlane) * 3;
            out[o + 0] = sm[SM_VP + vlane * 99 + bl * 3 + 0];
            out[o + 1] = sm[SM_VP + vlane * 99 + bl * 3 + 1];
            out[o + 2] = sm[SM_VP + vlane * 99 + bl * 3 + 2];
        }
    }
}

// ---------------- launch ----------------
extern "C" void kernel_launch(void* const* d_in, const int* in_sizes, int n_in,
                              void* d_out, int out_size)
{
    const float* pose    = (const float*)d_in[0];
    const float* betas   = (const float*)d_in[1];
    const float* trans   = (const float*)d_in[2];
    const float* v_temp  = (const float*)d_in[3];
    const float* sdirs   = (const float*)d_in[4];
    const float* pdirs   = (const float*)d_in[5];
    const float* Jreg    = (const float*)d_in[6];
    const float* wts     = (const float*)d_in[7];
    float* out = (float*)d_out;
    float* outJt = out + (size_t)3 * BATCH * NV * 3;

    k0_js<<<NJ, 256>>>(Jreg, sdirs, v_temp);
    k1_batch<<<BATCH, 32>>>(pose, betas, trans, outJt);
    cudaFuncSetAttribute(k2_main, cudaFuncAttributeMaxDynamicSharedMemorySize, SMEM_BYTES);
    dim3 grid((NV + 31) / 32, BATCH / 32);
    k2_main<<<grid, 128, SMEM_BYTES>>>(betas, v_temp, sdirs, pdirs, wts, out);
}

// round 2
// speedup vs baseline: 1.0219x; 1.0219x over previous
#include <cuda_runtime.h>
#include <math.h>

#define BATCH 1024
#define NV    6890
#define NJ    24

typedef unsigned long long ull;

// ---------------- packed f32x2 helpers ----------------
__device__ __forceinline__ ull pk(float lo, float hi) {
    ull r; asm("mov.b64 %0,{%1,%2};" : "=l"(r) : "f"(lo), "f"(hi)); return r;
}
__device__ __forceinline__ void unpk(ull v, float& a, float& b) {
    asm("mov.b64 {%0,%1},%2;" : "=f"(a), "=f"(b) : "l"(v));
}
__device__ __forceinline__ void fma2(ull& d, ull a, ull b) {
    asm("fma.rn.f32x2 %0,%1,%2,%0;" : "+l"(d) : "l"(a), "l"(b));
}
__device__ __forceinline__ ull fma2n(ull a, ull b, ull c) {
    ull d; asm("fma.rn.f32x2 %0,%1,%2,%3;" : "=l"(d) : "l"(a), "l"(b), "l"(c)); return d;
}

// ---------------- scratch (device globals; no allocation) ----------------
__device__ float g_JS[NJ * 30];      // J_regressor @ shapedirs  [j][k][n]
__device__ float g_JT[NJ * 3];       // J_regressor @ v_template [j][k]
__device__ float g_PF[BATCH * 96];   // pose_feat padded to 96 (93..95 = 0)
__device__ float g_GS[BATCH * 288];  // skinning matrices [b][j][3][4], trans folded in
__device__ float g_part[8][NJ][33];  // k0 partials

__constant__ int c_par[24] = {-1,0,0,0,1,2,3,4,5,6,7,8,9,9,9,12,13,14,16,17,18,19,20,21};

// ---------------- kernel 0a: partial JS/JT reduction (24 x 8 chunks) ----------------
__global__ void k0a(const float* __restrict__ Jreg,
                    const float* __restrict__ sdirs,
                    const float* __restrict__ vtemp)
{
    int j = blockIdx.x;
    int ch = blockIdx.y;
    int t = threadIdx.x;
    int v0 = ch * 862;
    int v1 = v0 + 862; if (v1 > NV) v1 = NV;
    float acc[33];
#pragma unroll
    for (int p = 0; p < 33; ++p) acc[p] = 0.f;
    for (int v = v0 + t; v < v1; v += 256) {
        float jr = Jreg[j * NV + v];
        const float* sp = sdirs + v * 30;
#pragma unroll
        for (int p = 0; p < 30; ++p) acc[p] = fmaf(jr, sp[p], acc[p]);
        const float* vp = vtemp + v * 3;
#pragma unroll
        for (int k = 0; k < 3; ++k) acc[30 + k] = fmaf(jr, vp[k], acc[30 + k]);
    }
    __shared__ float red[256][33];
#pragma unroll
    for (int p = 0; p < 33; ++p) red[t][p] = acc[p];
    __syncthreads();
    for (int off = 128; off >= 1; off >>= 1) {
        if (t < off) {
#pragma unroll
            for (int p = 0; p < 33; ++p) red[t][p] += red[t + off][p];
        }
        __syncthreads();
    }
    if (t < 33) g_part[ch][j][t] = red[0][t];
}

// ---------------- kernel 0b: combine partials ----------------
__global__ void k0b()
{
    int j = blockIdx.x;
    int t = threadIdx.x;
    if (t < 33) {
        float s = 0.f;
#pragma unroll
        for (int c = 0; c < 8; ++c) s += g_part[c][j][t];
        if (t < 30) g_JS[j * 30 + t] = s;
        else        g_JT[j * 3 + (t - 30)] = s;
    }
}

// ---------------- kernel 1: per-batch pose feat, R, J, chain, G_skin ----------------
__global__ void k1_batch(const float* __restrict__ pose,
                         const float* __restrict__ betas,
                         const float* __restrict__ trans,
                         float* __restrict__ outJt)
{
    int b = blockIdx.x;
    int lane = threadIdx.x;
    __shared__ float Rm[24][9];
    __shared__ float Jm[24][3];
    __shared__ float Gm[24][12];
    __shared__ float bet[10];
    if (lane < 10) bet[lane] = betas[b * 10 + lane];
    __syncwarp();
    if (lane < 24) {
        float tx = pose[b * 72 + lane * 3 + 0];
        float ty = pose[b * 72 + lane * 3 + 1];
        float tz = pose[b * 72 + lane * 3 + 2];
        float ax = tx + 1e-8f, ay = ty + 1e-8f, az = tz + 1e-8f;
        float angle = sqrtf(ax * ax + ay * ay + az * az);
        float inv = 1.f / angle;
        float nx = tx * inv, ny = ty * inv, nz = tz * inv;
        float half = 0.5f * angle;
        float s = sinf(half), c = cosf(half);
        if (lane > 0) {
            float* pfo = g_PF + b * 96 + lane * 4 - 4;
            pfo[0] = s * nx; pfo[1] = s * ny; pfo[2] = s * nz; pfo[3] = c - 1.f;
        }
        float qw = c, qx = s * nx, qy = s * ny, qz = s * nz;
        float qn = rsqrtf(qw * qw + qx * qx + qy * qy + qz * qz);
        qw *= qn; qx *= qn; qy *= qn; qz *= qn;
        float w2 = qw * qw, x2 = qx * qx, y2 = qy * qy, z2 = qz * qz;
        float wx = qw * qx, wy = qw * qy, wz = qw * qz;
        float xy = qx * qy, xz = qx * qz, yz = qy * qz;
        Rm[lane][0] = w2 + x2 - y2 - z2; Rm[lane][1] = 2.f*xy - 2.f*wz; Rm[lane][2] = 2.f*wy + 2.f*xz;
        Rm[lane][3] = 2.f*wz + 2.f*xy;  Rm[lane][4] = w2 - x2 + y2 - z2; Rm[lane][5] = 2.f*yz - 2.f*wx;
        Rm[lane][6] = 2.f*xz - 2.f*wy;  Rm[lane][7] = 2.f*wx + 2.f*yz;  Rm[lane][8] = w2 - x2 - y2 + z2;
#pragma unroll
        for (int k = 0; k < 3; ++k) {
            float jv = g_JT[lane * 3 + k];
#pragma unroll
            for (int n = 0; n < 10; ++n) jv = fmaf(g_JS[lane * 30 + k * 10 + n], bet[n], jv);
            Jm[lane][k] = jv;
        }
    } else if (lane == 24) {
        g_PF[b * 96 + 92] = bet[1];
        g_PF[b * 96 + 93] = 0.f; g_PF[b * 96 + 94] = 0.f; g_PF[b * 96 + 95] = 0.f;
    }
    __syncwarp();
    if (lane < 12) {
        int r = lane >> 2, cc = lane & 3;
        Gm[0][lane] = (cc < 3) ? Rm[0][r * 3 + cc] : Jm[0][r];
    }
    __syncwarp();
    for (int i = 1; i < NJ; ++i) {
        int p = c_par[i];
        if (lane < 12) {
            int r = lane >> 2, cc = lane & 3;
            float l0, l1, l2, add = 0.f;
            if (cc < 3) { l0 = Rm[i][cc]; l1 = Rm[i][3 + cc]; l2 = Rm[i][6 + cc]; }
            else {
                l0 = Jm[i][0] - Jm[p][0]; l1 = Jm[i][1] - Jm[p][1]; l2 = Jm[i][2] - Jm[p][2];
                add = Gm[p][r * 4 + 3];
            }
            Gm[i][lane] = fmaf(Gm[p][r*4+0], l0, fmaf(Gm[p][r*4+1], l1, fmaf(Gm[p][r*4+2], l2, add)));
        }
        __syncwarp();
    }
    float t0 = trans[b * 3 + 0], t1 = trans[b * 3 + 1], t2 = trans[b * 3 + 2];
    if (lane < 24) {
        outJt[(b * 24 + lane) * 3 + 0] = Gm[lane][3]  + t0;
        outJt[(b * 24 + lane) * 3 + 1] = Gm[lane][7]  + t1;
        outJt[(b * 24 + lane) * 3 + 2] = Gm[lane][11] + t2;
    }
    __syncwarp();
    for (int idx = lane; idx < 288; idx += 32) {
        int j = idx / 12, e = idx % 12;
        int r = e >> 2, cc = e & 3;
        float val = Gm[j][e];
        if (cc == 3) {
            val = Gm[j][r*4+3] - (Gm[j][r*4+0]*Jm[j][0] + Gm[j][r*4+1]*Jm[j][1] + Gm[j][r*4+2]*Jm[j][2]);
            val += (r == 0 ? t0 : (r == 1 ? t1 : t2));
        }
        g_GS[b * 288 + idx] = val;
    }
}

// ---------------- kernel 2: the heavy fused kernel (packed f32x2) ----------------
// smem layout (floats); all offsets multiple of 4 (16B aligned)
#define SM_PD  0        // 9344 : posedirs [v][292] (k-stride 96, f padded 93->96)
#define SM_PF  9344     // 3072 : pose_feat [32][96]
#define SM_GS2 12416    // 9344 : G pair-interleaved [pp(16)][584] : j*24 + e*2 + h
#define SM_SD  21760    // 1088 : shapedirs [v][34]
#define SM_WT  22848    // 800  : weights [v][25]
#define SM_VT  23648    // 96   : v_template [v][3]
#define SM_BT  23744    // 320  : betas [b][10]
#define SM_VP  24064    // 3264 : staging pair-interleaved [v][102] : pp*6 + k*2 + h
#define SM_TOTAL 27328
#define SMEM_BYTES (SM_TOTAL * 4)

__global__ void __launch_bounds__(128) k2_main(
    const float* __restrict__ betas,
    const float* __restrict__ v_template,
    const float* __restrict__ shapedirs,
    const float* __restrict__ posedirs,
    const float* __restrict__ weights,
    float* __restrict__ out)
{
    extern __shared__ float sm[];
    const int tid = threadIdx.x;
    const int vt0 = blockIdx.x * 32;
    const int bt0 = blockIdx.y * 32;
    const int nv = (NV - vt0) < 32 ? (NV - vt0) : 32;

    // ---- cooperative staging ----
    {
        // posedirs: coalesced gmem read, scattered smem write into padded layout
        int cnt = nv * 279;
        int base = vt0 * 279;
        for (int i = tid; i < cnt; i += 128) {
            int v = i / 279, r = i % 279;
            int k = r / 93, f = r % 93;
            sm[SM_PD + v * 292 + k * 96 + f] = posedirs[base + i];
        }
        // zero padding f=93..95 for all v,k (pf there is 0; avoid NaN*0)
        for (int i = tid; i < 32 * 9; i += 128) {
            int v = i / 9, r = i % 9;
            sm[SM_PD + v * 292 + (r / 3) * 96 + 93 + (r % 3)] = 0.f;
        }
        for (int i = tid; i < 32 * 96; i += 128) sm[SM_PF + i] = g_PF[bt0 * 96 + i];
        for (int i = tid; i < 32 * 288; i += 128) {
            int b = i / 288, e = i % 288;
            sm[SM_GS2 + (b >> 1) * 584 + e * 2 + (b & 1)] = g_GS[bt0 * 288 + i];
        }
        for (int i = tid; i < nv * 30; i += 128) {
            int v = i / 30, n = i % 30;
            sm[SM_SD + v * 34 + n] = shapedirs[vt0 * 30 + i];
        }
        for (int i = tid; i < nv * 24; i += 128) {
            int v = i / 24, j = i % 24;
            sm[SM_WT + v * 25 + j] = weights[vt0 * 24 + i];
        }
        for (int i = tid; i < nv * 3; i += 128) sm[SM_VT + i] = v_template[vt0 * 3 + i];
        for (int i = tid; i < 32 * 10; i += 128) sm[SM_BT + i] = betas[bt0 * 10 + i];
    }
    __syncthreads();

    const int vlane = tid & 31;
    const int wq = tid >> 5;                  // warp -> batches {wq, wq+4, ...}
    const bool valid = (vt0 + vlane) < NV;
    const size_t R1 = (size_t)BATCH * NV * 3; // v_posed region
    const size_t R2 = 2 * R1;                 // v_shaped region

    ull acc2[3][8];                            // packed (even-f, odd-f) partial sums
    // ---- phase 1a: v_shaped (packed over feature pairs) ----
    {
        ull sdr2[15];
#pragma unroll
        for (int p = 0; p < 15; ++p)
            sdr2[p] = *reinterpret_cast<const ull*>(sm + SM_SD + vlane * 34 + p * 2);
        float vtr0 = sm[SM_VT + vlane * 3 + 0];
        float vtr1 = sm[SM_VT + vlane * 3 + 1];
        float vtr2 = sm[SM_VT + vlane * 3 + 2];
#pragma unroll
        for (int bb = 0; bb < 8; ++bb) {
            int bl = wq + bb * 4;
            ull a0 = pk(vtr0, 0.f), a1 = pk(vtr1, 0.f), a2 = pk(vtr2, 0.f);
#pragma unroll
            for (int np = 0; np < 5; ++np) {
                ull be2 = *reinterpret_cast<const ull*>(sm + SM_BT + bl * 10 + np * 2);
                fma2(a0, sdr2[np], be2);
                fma2(a1, sdr2[5 + np], be2);
                fma2(a2, sdr2[10 + np], be2);
            }
            if (valid) {
                float l0, h0, l1, h1, l2, h2;
                unpk(a0, l0, h0); unpk(a1, l1, h1); unpk(a2, l2, h2);
                size_t o = ((size_t)(bt0 + bl) * NV + vt0 + vlane) * 3;
                out[R2 + o + 0] = l0 + h0;
                out[R2 + o + 1] = l1 + h1;
                out[R2 + o + 2] = l2 + h2;
            }
            acc2[0][bb] = a0; acc2[1][bb] = a1; acc2[2][bb] = a2;
        }
    }
    // ---- phase 1b: posedirs blend, packed over feature pairs ----
    {
        const float* pdp = sm + SM_PD + vlane * 292;
        for (int f = 0; f < 96; f += 4) {
            ulonglong2 pf2[8];
#pragma unroll
            for (int bb = 0; bb < 8; ++bb)
                pf2[bb] = *reinterpret_cast<const ulonglong2*>(sm + SM_PF + (wq + bb * 4) * 96 + f);
#pragma unroll
            for (int k = 0; k < 3; ++k) {
                ulonglong2 pd2 = *reinterpret_cast<const ulonglong2*>(pdp + k * 96 + f);
#pragma unroll
                for (int bb = 0; bb < 8; ++bb) {
                    fma2(acc2[k][bb], pd2.x, pf2[bb].x);
                    fma2(acc2[k][bb], pd2.y, pf2[bb].y);
                }
            }
        }
    }
    // ---- fold, store v_posed, stage pair-interleaved for skinning ----
#pragma unroll
    for (int bb = 0; bb < 8; ++bb) {
        int bl = wq + bb * 4;
        float s[3];
#pragma unroll
        for (int k = 0; k < 3; ++k) {
            float lo, hi; unpk(acc2[k][bb], lo, hi);
            s[k] = lo + hi;
        }
        if (valid) {
            size_t o = ((size_t)(bt0 + bl) * NV + vt0 + vlane) * 3;
            out[R1 + o + 0] = s[0];
            out[R1 + o + 1] = s[1];
            out[R1 + o + 2] = s[2];
        }
        int pp = bl >> 1, h = bl & 1;
#pragma unroll
        for (int k = 0; k < 3; ++k)
            sm[SM_VP + vlane * 102 + pp * 6 + k * 2 + h] = s[k];
    }
    __syncthreads();
    // ---- phase 2: skinning, 4 vertices x 1 batch-pair per thread, packed over pair ----
    {
        const int vset = (tid & 7) * 4;
        const int pp = tid >> 3;
        ull vh[4][3];
#pragma unroll
        for (int vi = 0; vi < 4; ++vi)
#pragma unroll
            for (int k = 0; k < 3; ++k)
                vh[vi][k] = *reinterpret_cast<const ull*>(sm + SM_VP + (vset + vi) * 102 + pp * 6 + k * 2);
        ull av[4][3];
#pragma unroll
        for (int vi = 0; vi < 4; ++vi)
#pragma unroll
            for (int k = 0; k < 3; ++k) av[vi][k] = 0ull;
#pragma unroll 4
        for (int j = 0; j < 24; ++j) {
            const float* gp = sm + SM_GS2 + pp * 584 + j * 24;
            ulonglong2 ga = *reinterpret_cast<const ulonglong2*>(gp);       // r0c0,r0c1
            ulonglong2 gb = *reinterpret_cast<const ulonglong2*>(gp + 4);   // r0c2,r0c3
            ulonglong2 gc = *reinterpret_cast<const ulonglong2*>(gp + 8);   // r1c0,r1c1
            ulonglong2 gd = *reinterpret_cast<const ulonglong2*>(gp + 12);  // r1c2,r1c3
            ulonglong2 ge = *reinterpret_cast<const ulonglong2*>(gp + 16);  // r2c0,r2c1
            ulonglong2 gf = *reinterpret_cast<const ulonglong2*>(gp + 20);  // r2c2,r2c3
#pragma unroll
            for (int vi = 0; vi < 4; ++vi) {
                float w = sm[SM_WT + (vset + vi) * 25 + j];
                ull wd = pk(w, w);
                ull tx = fma2n(ga.x, vh[vi][0], fma2n(ga.y, vh[vi][1], fma2n(gb.x, vh[vi][2], gb.y)));
                ull ty = fma2n(gc.x, vh[vi][0], fma2n(gc.y, vh[vi][1], fma2n(gd.x, vh[vi][2], gd.y)));
                ull tz = fma2n(ge.x, vh[vi][0], fma2n(ge.y, vh[vi][1], fma2n(gf.x, vh[vi][2], gf.y)));
                fma2(av[vi][0], wd, tx);
                fma2(av[vi][1], wd, ty);
                fma2(av[vi][2], wd, tz);
            }
        }
#pragma unroll
        for (int vi = 0; vi < 4; ++vi)
#pragma unroll
            for (int k = 0; k < 3; ++k)
                *reinterpret_cast<ull*>(sm + SM_VP + (vset + vi) * 102 + pp * 6 + k * 2) = av[vi][k];
    }
    __syncthreads();
    // ---- phase 3: store v ----
#pragma unroll
    for (int bb = 0; bb < 8; ++bb) {
        int bl = wq + bb * 4;
        if (valid) {
            int pp = bl >> 1, h = bl & 1;
            size_t o = ((size_t)(bt0 + bl) * NV + vt0 + vlane) * 3;
            out[o + 0] = sm[SM_VP + vlane * 102 + pp * 6 + 0 + h];
            out[o + 1] = sm[SM_VP + vlane * 102 + pp * 6 + 2 + h];
            out[o + 2] = sm[SM_VP + vlane * 102 + pp * 6 + 4 + h];
        }
    }
}

// ---------------- launch ----------------
extern "C" void kernel_launch(void* const* d_in, const int* in_sizes, int n_in,
                              void* d_out, int out_size)
{
    const float* pose    = (const float*)d_in[0];
    const float* betas   = (const float*)d_in[1];
    const float* trans   = (const float*)d_in[2];
    const float* v_temp  = (const float*)d_in[3];
    const float* sdirs   = (const float*)d_in[4];
    const float* pdirs   = (const float*)d_in[5];
    const float* Jreg    = (const float*)d_in[6];
    const float* wts     = (const float*)d_in[7];
    float* out = (float*)d_out;
    float* outJt = out + (size_t)3 * BATCH * NV * 3;

    k0a<<<dim3(NJ, 8), 256>>>(Jreg, sdirs, v_temp);
    k0b<<<NJ, 64>>>();
    k1_batch<<<BATCH, 32>>>(pose, betas, trans, outJt);
    cudaFuncSetAttribute(k2_main, cudaFuncAttributeMaxDynamicSharedMemorySize, SMEM_BYTES);
    dim3 grid((NV + 31) / 32, BATCH / 32);
    k2_main<<<grid, 128, SMEM_BYTES>>>(betas, v_temp, sdirs, pdirs, wts, out);
}

// round 3
// speedup vs baseline: 1.0856x; 1.0624x over previous
#include <cuda_runtime.h>
#include <math.h>

#define BATCH 1024
#define NV    6890
#define NJ    24

typedef unsigned long long ull;

// ---------------- packed f32x2 helpers ----------------
__device__ __forceinline__ ull pk(float lo, float hi) {
    ull r; asm("mov.b64 %0,{%1,%2};" : "=l"(r) : "f"(lo), "f"(hi)); return r;
}
__device__ __forceinline__ void unpk(ull v, float& a, float& b) {
    asm("mov.b64 {%0,%1},%2;" : "=f"(a), "=f"(b) : "l"(v));
}
__device__ __forceinline__ void fma2(ull& d, ull a, ull b) {
    asm("fma.rn.f32x2 %0,%1,%2,%0;" : "+l"(d) : "l"(a), "l"(b));
}
__device__ __forceinline__ ull fma2n(ull a, ull b, ull c) {
    ull d; asm("fma.rn.f32x2 %0,%1,%2,%3;" : "=l"(d) : "l"(a), "l"(b), "l"(c)); return d;
}

// ---------------- scratch (device globals; no allocation) ----------------
__device__ float g_JS[NJ * 30];
__device__ float g_JT[NJ * 3];
__device__ float g_PF[BATCH * 96];
__device__ float g_GS[BATCH * 288];
__device__ float g_part[8][NJ][33];

__constant__ int c_par[24] = {-1,0,0,0,1,2,3,4,5,6,7,8,9,9,9,12,13,14,16,17,18,19,20,21};

// ---------------- kernel 0a: partial JS/JT reduction ----------------
__global__ void k0a(const float* __restrict__ Jreg,
                    const float* __restrict__ sdirs,
                    const float* __restrict__ vtemp)
{
    int j = blockIdx.x;
    int ch = blockIdx.y;
    int t = threadIdx.x;
    int v0 = ch * 862;
    int v1 = v0 + 862; if (v1 > NV) v1 = NV;
    float acc[33];
#pragma unroll
    for (int p = 0; p < 33; ++p) acc[p] = 0.f;
    for (int v = v0 + t; v < v1; v += 256) {
        float jr = Jreg[j * NV + v];
        const float* sp = sdirs + v * 30;
#pragma unroll
        for (int p = 0; p < 30; ++p) acc[p] = fmaf(jr, sp[p], acc[p]);
        const float* vp = vtemp + v * 3;
#pragma unroll
        for (int k = 0; k < 3; ++k) acc[30 + k] = fmaf(jr, vp[k], acc[30 + k]);
    }
    __shared__ float red[256][33];
#pragma unroll
    for (int p = 0; p < 33; ++p) red[t][p] = acc[p];
    __syncthreads();
    for (int off = 128; off >= 1; off >>= 1) {
        if (t < off) {
#pragma unroll
            for (int p = 0; p < 33; ++p) red[t][p] += red[t + off][p];
        }
        __syncthreads();
    }
    if (t < 33) g_part[ch][j][t] = red[0][t];
}

__global__ void k0b()
{
    int j = blockIdx.x;
    int t = threadIdx.x;
    if (t < 33) {
        float s = 0.f;
#pragma unroll
        for (int c = 0; c < 8; ++c) s += g_part[c][j][t];
        if (t < 30) g_JS[j * 30 + t] = s;
        else        g_JT[j * 3 + (t - 30)] = s;
    }
}

// ---------------- kernel 1: per-batch chain ----------------
__global__ void k1_batch(const float* __restrict__ pose,
                         const float* __restrict__ betas,
                         const float* __restrict__ trans,
                         float* __restrict__ outJt)
{
    int b = blockIdx.x;
    int lane = threadIdx.x;
    __shared__ float Rm[24][9];
    __shared__ float Jm[24][3];
    __shared__ float Gm[24][12];
    __shared__ float bet[10];
    if (lane < 10) bet[lane] = betas[b * 10 + lane];
    __syncwarp();
    if (lane < 24) {
        float tx = pose[b * 72 + lane * 3 + 0];
        float ty = pose[b * 72 + lane * 3 + 1];
        float tz = pose[b * 72 + lane * 3 + 2];
        float ax = tx + 1e-8f, ay = ty + 1e-8f, az = tz + 1e-8f;
        float angle = sqrtf(ax * ax + ay * ay + az * az);
        float inv = 1.f / angle;
        float nx = tx * inv, ny = ty * inv, nz = tz * inv;
        float half = 0.5f * angle;
        float s = sinf(half), c = cosf(half);
        if (lane > 0) {
            float* pfo = g_PF + b * 96 + lane * 4 - 4;
            pfo[0] = s * nx; pfo[1] = s * ny; pfo[2] = s * nz; pfo[3] = c - 1.f;
        }
        float qw = c, qx = s * nx, qy = s * ny, qz = s * nz;
        float qn = rsqrtf(qw * qw + qx * qx + qy * qy + qz * qz);
        qw *= qn; qx *= qn; qy *= qn; qz *= qn;
        float w2 = qw * qw, x2 = qx * qx, y2 = qy * qy, z2 = qz * qz;
        float wx = qw * qx, wy = qw * qy, wz = qw * qz;
        float xy = qx * qy, xz = qx * qz, yz = qy * qz;
        Rm[lane][0] = w2 + x2 - y2 - z2; Rm[lane][1] = 2.f*xy - 2.f*wz; Rm[lane][2] = 2.f*wy + 2.f*xz;
        Rm[lane][3] = 2.f*wz + 2.f*xy;  Rm[lane][4] = w2 - x2 + y2 - z2; Rm[lane][5] = 2.f*yz - 2.f*wx;
        Rm[lane][6] = 2.f*xz - 2.f*wy;  Rm[lane][7] = 2.f*wx + 2.f*yz;  Rm[lane][8] = w2 - x2 - y2 + z2;
#pragma unroll
        for (int k = 0; k < 3; ++k) {
            float jv = g_JT[lane * 3 + k];
#pragma unroll
            for (int n = 0; n < 10; ++n) jv = fmaf(g_JS[lane * 30 + k * 10 + n], bet[n], jv);
            Jm[lane][k] = jv;
        }
    } else if (lane == 24) {
        g_PF[b * 96 + 92] = bet[1];
        g_PF[b * 96 + 93] = 0.f; g_PF[b * 96 + 94] = 0.f; g_PF[b * 96 + 95] = 0.f;
    }
    __syncwarp();
    if (lane < 12) {
        int r = lane >> 2, cc = lane & 3;
        Gm[0][lane] = (cc < 3) ? Rm[0][r * 3 + cc] : Jm[0][r];
    }
    __syncwarp();
    for (int i = 1; i < NJ; ++i) {
        int p = c_par[i];
        if (lane < 12) {
            int r = lane >> 2, cc = lane & 3;
            float l0, l1, l2, add = 0.f;
            if (cc < 3) { l0 = Rm[i][cc]; l1 = Rm[i][3 + cc]; l2 = Rm[i][6 + cc]; }
            else {
                l0 = Jm[i][0] - Jm[p][0]; l1 = Jm[i][1] - Jm[p][1]; l2 = Jm[i][2] - Jm[p][2];
                add = Gm[p][r * 4 + 3];
            }
            Gm[i][lane] = fmaf(Gm[p][r*4+0], l0, fmaf(Gm[p][r*4+1], l1, fmaf(Gm[p][r*4+2], l2, add)));
        }
        __syncwarp();
    }
    float t0 = trans[b * 3 + 0], t1 = trans[b * 3 + 1], t2 = trans[b * 3 + 2];
    if (lane < 24) {
        outJt[(b * 24 + lane) * 3 + 0] = Gm[lane][3]  + t0;
        outJt[(b * 24 + lane) * 3 + 1] = Gm[lane][7]  + t1;
        outJt[(b * 24 + lane) * 3 + 2] = Gm[lane][11] + t2;
    }
    __syncwarp();
    for (int idx = lane; idx < 288; idx += 32) {
        int j = idx / 12, e = idx % 12;
        int r = e >> 2, cc = e & 3;
        float val = Gm[j][e];
        if (cc == 3) {
            val = Gm[j][r*4+3] - (Gm[j][r*4+0]*Jm[j][0] + Gm[j][r*4+1]*Jm[j][1] + Gm[j][r*4+2]*Jm[j][2]);
            val += (r == 0 ? t0 : (r == 1 ? t1 : t2));
        }
        g_GS[b * 288 + idx] = val;
    }
}

// ---------------- kernel 2: heavy fused kernel, 256 threads ----------------
// smem layout (floats), 16B-aligned bases
#define SM_PD  0        // 9344 : posedirs [v][292] (k-stride 96, f padded 93->96)
#define SM_PF  9344     // 3072 : pose_feat [32][96]
#define SM_GS2 12416    // 9344 : G pair-interleaved [pp(16)][584] : j*24 + e*2 + h
#define SM_SD  21760    // 1088 : shapedirs [v][34]
#define SM_W2  22848    // 1664 : weights duplicated [v][52] : j*2 {w,w}
#define SM_VT  24512    // 96
#define SM_BT  24608    // 320
#define SM_VP  24928    // 3264 : staging pair-interleaved [v][102] : pp*6 + k*2 + h
#define SM_TOTAL 28192
#define SMEM_BYTES (SM_TOTAL * 4)

__global__ void __launch_bounds__(256, 2) k2_main(
    const float* __restrict__ betas,
    const float* __restrict__ v_template,
    const float* __restrict__ shapedirs,
    const float* __restrict__ posedirs,
    const float* __restrict__ weights,
    float* __restrict__ out)
{
    extern __shared__ float sm[];
    const int tid = threadIdx.x;
    const int vt0 = blockIdx.x * 32;
    const int bt0 = blockIdx.y * 32;
    const int nv = (NV - vt0) < 32 ? (NV - vt0) : 32;

    // ---- cooperative staging ----
    {
        int cnt = nv * 279;
        int base = vt0 * 279;
        for (int i = tid; i < cnt; i += 256) {
            int v = i / 279, r = i % 279;
            int k = r / 93, f = r % 93;
            sm[SM_PD + v * 292 + k * 96 + f] = posedirs[base + i];
        }
        for (int i = tid; i < 32 * 9; i += 256) {
            int v = i / 9, r = i % 9;
            sm[SM_PD + v * 292 + (r / 3) * 96 + 93 + (r % 3)] = 0.f;
        }
        for (int i = tid; i < 32 * 96; i += 256) sm[SM_PF + i] = g_PF[bt0 * 96 + i];
        for (int i = tid; i < 32 * 288; i += 256) {
            int b = i / 288, e = i % 288;
            sm[SM_GS2 + (b >> 1) * 584 + e * 2 + (b & 1)] = g_GS[bt0 * 288 + i];
        }
        for (int i = tid; i < nv * 30; i += 256) {
            int v = i / 30, n = i % 30;
            sm[SM_SD + v * 34 + n] = shapedirs[vt0 * 30 + i];
        }
        for (int i = tid; i < nv * 24; i += 256) {
            int v = i / 24, j = i % 24;
            float w = weights[vt0 * 24 + i];
            sm[SM_W2 + v * 52 + j * 2 + 0] = w;
            sm[SM_W2 + v * 52 + j * 2 + 1] = w;
        }
        for (int i = tid; i < nv * 3; i += 256) sm[SM_VT + i] = v_template[vt0 * 3 + i];
        for (int i = tid; i < 32 * 10; i += 256) sm[SM_BT + i] = betas[bt0 * 10 + i];
    }
    __syncthreads();

    const int vlane = tid & 31;
    const int wq = tid >> 5;                  // warp -> batches {wq, wq+8, wq+16, wq+24}
    const bool valid = (vt0 + vlane) < NV;
    const size_t R1 = (size_t)BATCH * NV * 3;
    const size_t R2 = 2 * R1;

    ull acc2[3][4];
    // ---- phase 1a: v_shaped (packed over feature pairs) ----
    {
        ull sdr2[15];
#pragma unroll
        for (int p = 0; p < 15; ++p)
            sdr2[p] = *reinterpret_cast<const ull*>(sm + SM_SD + vlane * 34 + p * 2);
        float vtr0 = sm[SM_VT + vlane * 3 + 0];
        float vtr1 = sm[SM_VT + vlane * 3 + 1];
        float vtr2 = sm[SM_VT + vlane * 3 + 2];
#pragma unroll
        for (int bb = 0; bb < 4; ++bb) {
            int bl = wq + bb * 8;
            ull a0 = pk(vtr0, 0.f), a1 = pk(vtr1, 0.f), a2 = pk(vtr2, 0.f);
#pragma unroll
            for (int np = 0; np < 5; ++np) {
                ull be2 = *reinterpret_cast<const ull*>(sm + SM_BT + bl * 10 + np * 2);
                fma2(a0, sdr2[np], be2);
                fma2(a1, sdr2[5 + np], be2);
                fma2(a2, sdr2[10 + np], be2);
            }
            if (valid) {
                float l0, h0, l1, h1, l2, h2;
                unpk(a0, l0, h0); unpk(a1, l1, h1); unpk(a2, l2, h2);
                size_t o = ((size_t)(bt0 + bl) * NV + vt0 + vlane) * 3;
                out[R2 + o + 0] = l0 + h0;
                out[R2 + o + 1] = l1 + h1;
                out[R2 + o + 2] = l2 + h2;
            }
            acc2[0][bb] = a0; acc2[1][bb] = a1; acc2[2][bb] = a2;
        }
    }
    // ---- phase 1b: posedirs blend, packed over feature pairs ----
    {
        const float* pdp = sm + SM_PD + vlane * 292;
        const float* pfp = sm + SM_PF + wq * 96;
#pragma unroll 8
        for (int f = 0; f < 96; f += 4) {
            ulonglong2 pf2[4];
#pragma unroll
            for (int bb = 0; bb < 4; ++bb)
                pf2[bb] = *reinterpret_cast<const ulonglong2*>(pfp + bb * 768 + f);
#pragma unroll
            for (int k = 0; k < 3; ++k) {
                ulonglong2 pd2 = *reinterpret_cast<const ulonglong2*>(pdp + k * 96 + f);
#pragma unroll
                for (int bb = 0; bb < 4; ++bb) {
                    fma2(acc2[k][bb], pd2.x, pf2[bb].x);
                    fma2(acc2[k][bb], pd2.y, pf2[bb].y);
                }
            }
        }
    }
    // ---- fold, store v_posed, stage pair-interleaved ----
#pragma unroll
    for (int bb = 0; bb < 4; ++bb) {
        int bl = wq + bb * 8;
        float s[3];
#pragma unroll
        for (int k = 0; k < 3; ++k) {
            float lo, hi; unpk(acc2[k][bb], lo, hi);
            s[k] = lo + hi;
        }
        if (valid) {
            size_t o = ((size_t)(bt0 + bl) * NV + vt0 + vlane) * 3;
            out[R1 + o + 0] = s[0];
            out[R1 + o + 1] = s[1];
            out[R1 + o + 2] = s[2];
        }
        int pp = bl >> 1, h = bl & 1;
#pragma unroll
        for (int k = 0; k < 3; ++k)
            sm[SM_VP + vlane * 102 + pp * 6 + k * 2 + h] = s[k];
    }
    __syncthreads();
    // ---- phase 2: skinning, 2 vertices x 1 batch-pair per thread ----
    {
        const int vset = (tid & 15) * 2;
        const int pp = tid >> 4;
        ull vh[2][3];
#pragma unroll
        for (int vi = 0; vi < 2; ++vi)
#pragma unroll
            for (int k = 0; k < 3; ++k)
                vh[vi][k] = *reinterpret_cast<const ull*>(sm + SM_VP + (vset + vi) * 102 + pp * 6 + k * 2);
        ull av[2][3];
#pragma unroll
        for (int vi = 0; vi < 2; ++vi)
#pragma unroll
            for (int k = 0; k < 3; ++k) av[vi][k] = 0ull;
        const float* gbase = sm + SM_GS2 + pp * 584;
#pragma unroll 4
        for (int j = 0; j < 24; ++j) {
            const float* gp = gbase + j * 24;
            ulonglong2 ga = *reinterpret_cast<const ulonglong2*>(gp);
            ulonglong2 gb = *reinterpret_cast<const ulonglong2*>(gp + 4);
            ulonglong2 gc = *reinterpret_cast<const ulonglong2*>(gp + 8);
            ulonglong2 gd = *reinterpret_cast<const ulonglong2*>(gp + 12);
            ulonglong2 ge = *reinterpret_cast<const ulonglong2*>(gp + 16);
            ulonglong2 gf = *reinterpret_cast<const ulonglong2*>(gp + 20);
#pragma unroll
            for (int vi = 0; vi < 2; ++vi) {
                ull wd = *reinterpret_cast<const ull*>(sm + SM_W2 + (vset + vi) * 52 + j * 2);
                ull tx = fma2n(ga.x, vh[vi][0], fma2n(ga.y, vh[vi][1], fma2n(gb.x, vh[vi][2], gb.y)));
                ull ty = fma2n(gc.x, vh[vi][0], fma2n(gc.y, vh[vi][1], fma2n(gd.x, vh[vi][2], gd.y)));
                ull tz = fma2n(ge.x, vh[vi][0], fma2n(ge.y, vh[vi][1], fma2n(gf.x, vh[vi][2], gf.y)));
                fma2(av[vi][0], wd, tx);
                fma2(av[vi][1], wd, ty);
                fma2(av[vi][2], wd, tz);
            }
        }
#pragma unroll
        for (int vi = 0; vi < 2; ++vi)
#pragma unroll
            for (int k = 0; k < 3; ++k)
                *reinterpret_cast<ull*>(sm + SM_VP + (vset + vi) * 102 + pp * 6 + k * 2) = av[vi][k];
    }
    __syncthreads();
    // ---- phase 3: store v ----
#pragma unroll
    for (int bb = 0; bb < 4; ++bb) {
        int bl = wq + bb * 8;
        if (valid) {
            int pp = bl >> 1, h = bl & 1;
            size_t o = ((size_t)(bt0 + bl) * NV + vt0 + vlane) * 3;
            out[o + 0] = sm[SM_VP + vlane * 102 + pp * 6 + 0 + h];
            out[o + 1] = sm[SM_VP + vlane * 102 + pp * 6 + 2 + h];
            out[o + 2] = sm[SM_VP + vlane * 102 + pp * 6 + 4 + h];
        }
    }
}

// ---------------- launch ----------------
extern "C" void kernel_launch(void* const* d_in, const int* in_sizes, int n_in,
                              void* d_out, int out_size)
{
    const float* pose    = (const float*)d_in[0];
    const float* betas   = (const float*)d_in[1];
    const float* trans   = (const float*)d_in[2];
    const float* v_temp  = (const float*)d_in[3];
    const float* sdirs   = (const float*)d_in[4];
    const float* pdirs   = (const float*)d_in[5];
    const float* Jreg    = (const float*)d_in[6];
    const float* wts     = (const float*)d_in[7];
    float* out = (float*)d_out;
    float* outJt = out + (size_t)3 * BATCH * NV * 3;

    k0a<<<dim3(NJ, 8), 256>>>(Jreg, sdirs, v_temp);
    k0b<<<NJ, 64>>>();
    k1_batch<<<BATCH, 32>>>(pose, betas, trans, outJt);
    cudaFuncSetAttribute(k2_main, cudaFuncAttributeMaxDynamicSharedMemorySize, SMEM_BYTES);
    dim3 grid((NV + 31) / 32, BATCH / 32);
    k2_main<<<grid, 256, SMEM_BYTES>>>(betas, v_temp, sdirs, pdirs, wts, out);
}